// round 5
// baseline (speedup 1.0000x reference)
#include <cuda_runtime.h>
#include <math.h>
#include <stdint.h>

#define NB      16384
#define FANOUT  16
#define BE      (NB*FANOUT)
#define EMB     128
#define HID     256
#define NEDGE   16

#define BM      128
#define BN      128
#define KC      32
#define AP      36        // A smem pitch: banks (4q+c) conflict-free
#define BP      132       // B smem pitch: banks (4c+q) conflict-free, 16B-aligned rows

// ---- persistent scratch ----
__device__ float g_WsrcT_h[EMB*HID],  g_WsrcT_l[EMB*HID];
__device__ float g_WdstT_h[EMB*HID],  g_WdstT_l[EMB*HID];
__device__ float g_WselfT_h[EMB*HID], g_WselfT_l[EMB*HID];
__device__ float g_W2T_h[HID*HID],    g_W2T_l[HID*HID];
__device__ float g_WneighT_h[HID*HID],g_WneighT_l[HID*HID];
__device__ float g_relb2[NEDGE*HID];
__device__ float g_neigh[(size_t)NB*HID];

// ------------------------------------------------------------------
__device__ __forceinline__ float tf32_rna(float x) {
    uint32_t r;
    asm("cvt.rna.tf32.f32 %0, %1;" : "=r"(r) : "f"(x));
    return __uint_as_float(r);
}
__device__ __forceinline__ void split2(float x, float& h, float& l) {
    h = tf32_rna(x);
    l = tf32_rna(x - h);
}
__device__ __forceinline__ void mma8(float* d, const float* a, const float* b) {
    asm volatile("mma.sync.aligned.m16n8k8.row.col.f32.tf32.tf32.f32 "
        "{%0,%1,%2,%3},{%4,%5,%6,%7},{%8,%9},{%0,%1,%2,%3};"
        : "+f"(d[0]), "+f"(d[1]), "+f"(d[2]), "+f"(d[3])
        : "r"(__float_as_uint(a[0])), "r"(__float_as_uint(a[1])),
          "r"(__float_as_uint(a[2])), "r"(__float_as_uint(a[3])),
          "r"(__float_as_uint(b[0])), "r"(__float_as_uint(b[1])));
}
template<int N> __device__ __forceinline__ void cp_wait() {
    asm volatile("cp.async.wait_group %0;" :: "n"(N));
}
__device__ __forceinline__ void cp16(void* dst, const void* src) {
    uint32_t sa = (uint32_t)__cvta_generic_to_shared(dst);
    asm volatile("cp.async.cg.shared.global [%0], [%1], 16;" :: "r"(sa), "l"(src));
}

// ------------------------------------------------------------------
// prep: transpose + hi/lo split of weights into [K][N] layout
// ------------------------------------------------------------------
__global__ void prep_split(const float* __restrict__ Wsrc, const float* __restrict__ Wdst,
                           const float* __restrict__ W2,   const float* __restrict__ Wself,
                           const float* __restrict__ Wneigh) {
    int i = blockIdx.x * blockDim.x + threadIdx.x;
    if (i < EMB*HID) {
        int k = i / HID, n = i % HID;
        float h, l;
        split2(Wsrc [n*EMB + k], h, l); g_WsrcT_h [i] = h; g_WsrcT_l [i] = l;
        split2(Wdst [n*EMB + k], h, l); g_WdstT_h [i] = h; g_WdstT_l [i] = l;
        split2(Wself[n*EMB + k], h, l); g_WselfT_h[i] = h; g_WselfT_l[i] = l;
    }
    if (i < HID*HID) {
        int k = i / HID, n = i % HID;
        float h, l;
        split2(W2    [n*HID + k], h, l); g_W2T_h    [i] = h; g_W2T_l    [i] = l;
        split2(Wneigh[n*HID + k], h, l); g_WneighT_h[i] = h; g_WneighT_l[i] = l;
    }
}

__global__ void prep_relb2(const float* __restrict__ edge_emb,
                           const float* __restrict__ edge_lin_w,
                           const float* __restrict__ b2) {
    int n = threadIdx.x;
    for (int r = 0; r < NEDGE; r++) {
        float s = b2[n];
        #pragma unroll 4
        for (int k = 0; k < EMB; k++)
            s = fmaf(edge_emb[r*EMB + k], edge_lin_w[n*EMB + k], s);
        g_relb2[r*HID + n] = s;
    }
}

// ------------------------------------------------------------------
// producers
// ------------------------------------------------------------------
// async prefetch of one KC x BN weight chunk (hi+lo) into smem
__device__ __forceinline__ void prefetchB(float* Bh, float* Bl,
                                          const float* __restrict__ WTh,
                                          const float* __restrict__ WTl,
                                          int k0, int colbase, int tid) {
    int k  = tid >> 3;                // 0..31
    int n0 = (tid & 7) << 4;          // 0,16,...,112
    const float* sh = WTh + (size_t)(k0 + k)*HID + colbase + n0;
    const float* sl = WTl + (size_t)(k0 + k)*HID + colbase + n0;
    float* dh = Bh + k*BP + n0;
    float* dl = Bl + k*BP + n0;
    #pragma unroll
    for (int j = 0; j < 4; j++) {
        cp16(dh + 4*j, sh + 4*j);
        cp16(dl + 4*j, sl + 4*j);
    }
    asm volatile("cp.async.commit_group;");
}

// split v[16] and store into A tile (thread covers row m, k-range half*16..+15)
__device__ __forceinline__ void stageA_vals(float* Ah, float* Al,
                                            const float* v, int m, int half) {
    float* dh = Ah + m*AP + half*16;
    float* dl = Al + m*AP + half*16;
    #pragma unroll
    for (int j = 0; j < 4; j++) {
        float4 h, l;
        split2(v[4*j+0], h.x, l.x); split2(v[4*j+1], h.y, l.y);
        split2(v[4*j+2], h.z, l.z); split2(v[4*j+3], h.w, l.w);
        *(float4*)(dh + 4*j) = h;
        *(float4*)(dl + 4*j) = l;
    }
}

__device__ __forceinline__ void loadV_row(float* v, const float* rowPtr) {
    #pragma unroll
    for (int j = 0; j < 4; j++) {
        float4 t = ((const float4*)rowPtr)[j];
        v[4*j] = t.x; v[4*j+1] = t.y; v[4*j+2] = t.z; v[4*j+3] = t.w;
    }
}

// ------------------------------------------------------------------
// warp mma over one KC=32 chunk; 3xTF32 compensated (R3-proven layout)
// ------------------------------------------------------------------
__device__ __forceinline__ void mma_chunk(const float* __restrict__ Ah,
                                          const float* __restrict__ Al,
                                          const float* __restrict__ Bh,
                                          const float* __restrict__ Bl,
                                          float (&acc)[2][8][4],
                                          int wm, int wn, int lane) {
    int r0 = wm*32 + (lane >> 2);
    int c  = lane & 3;
    int nb = wn*64 + (lane >> 2);
    #pragma unroll
    for (int kk = 0; kk < KC; kk += 8) {
        float ah[2][4], al[2][4];
        #pragma unroll
        for (int mf = 0; mf < 2; mf++) {
            const float* ph = Ah + (r0 + mf*16)*AP + kk + c;
            ah[mf][0] = ph[0];      ah[mf][1] = ph[8*AP];
            ah[mf][2] = ph[4];      ah[mf][3] = ph[8*AP + 4];
            const float* pl = Al + (r0 + mf*16)*AP + kk + c;
            al[mf][0] = pl[0];      al[mf][1] = pl[8*AP];
            al[mf][2] = pl[4];      al[mf][3] = pl[8*AP + 4];
        }
        #pragma unroll
        for (int nf = 0; nf < 8; nf++) {
            const float* pb = Bh + (kk + c)*BP + nb + nf*8;
            float bh[2] = { pb[0], pb[4*BP] };
            const float* pl2 = Bl + (kk + c)*BP + nb + nf*8;
            float bl[2] = { pl2[0], pl2[4*BP] };
            #pragma unroll
            for (int mf = 0; mf < 2; mf++) {
                mma8(acc[mf][nf], ah[mf], bh);
                mma8(acc[mf][nf], al[mf], bh);
                mma8(acc[mf][nf], ah[mf], bl);
            }
        }
    }
}

#define DYN_FLOATS (2*BM*AP + 4*KC*BP)   // 9216 + 16896 = 26112 floats

// ------------------------------------------------------------------
// event kernel
// ------------------------------------------------------------------
__global__ __launch_bounds__(256, 2)
void ev_kernel(const int* __restrict__ nbr_ev,
               const int* __restrict__ ev_st, const int* __restrict__ ev_dt,
               const int* __restrict__ ev_et,
               const int* __restrict__ ev_sid, const int* __restrict__ ev_did,
               const int* __restrict__ ev_ts,  const float* __restrict__ ev_w,
               const float* __restrict__ emb0, const float* __restrict__ emb1,
               const float* __restrict__ mlp_w1, const float* __restrict__ mlp_b1) {
    extern __shared__ float smem[];
    float* Ah = smem;
    float* Al = Ah + BM*AP;
    float* Bhb[2] = { Al + BM*AP,            Al + BM*AP + 2*KC*BP };
    float* Blb[2] = { Al + BM*AP + KC*BP,    Al + BM*AP + 3*KC*BP };

    __shared__ int   s_src[BM], s_dst[BM];   // (id<<1)|type
    __shared__ float s_ts[BM], s_lw[BM], s_val[BM];
    __shared__ int   s_rel[BM];
    __shared__ float s_w1a[HID], s_w1b[HID], s_b1[HID];

    int tid  = threadIdx.x;
    int lane = tid & 31;
    int w    = tid >> 5;
    int wm   = w & 3, wn = w >> 2;
    int colbase = blockIdx.y * BN;
    int m = tid >> 1, half = tid & 1;

    if (tid < BM) {
        int ev = nbr_ev[blockIdx.x*BM + tid];
        int e  = ev < 0 ? 0 : ev;
        s_val[tid] = ev < 0 ? 0.f : 1.f;
        s_src[tid] = (ev_sid[e] << 1) | (ev_st[e] != 0);
        s_dst[tid] = (ev_did[e] << 1) | (ev_dt[e] != 0);
        s_rel[tid] = ev_et[e];
        s_ts[tid]  = (float)ev_ts[e] / 1000000.0f;
        s_lw[tid]  = log1pf(ev_w[e]);
    }
    s_w1a[tid] = mlp_w1[tid*2 + 0];
    s_w1b[tid] = mlp_w1[tid*2 + 1];
    s_b1[tid]  = mlp_b1[tid];

    prefetchB(Bhb[0], Blb[0], g_WsrcT_h, g_WsrcT_l, 0, colbase, tid);
    __syncthreads();

    float ts = s_ts[m], lw = s_lw[m];

    float acc[2][8][4];
    #pragma unroll
    for (int a = 0; a < 2; a++)
        #pragma unroll
        for (int b = 0; b < 8; b++)
            #pragma unroll
            for (int q = 0; q < 4; q++) acc[a][b][q] = 0.f;

    // v(0): src embedding, chunk 0
    float v[16];
    {
        int id = s_src[m];
        const float* rp = (id & 1 ? emb1 : emb0) + (size_t)(id >> 1)*EMB + half*16;
        loadV_row(v, rp);
    }

    int p = 0;
    #pragma unroll 1
    for (int t = 0; t < 16; t++) {
        stageA_vals(Ah, Al, v, m, half);
        if (t < 15) {
            int u = t + 1;
            const float *WTh, *WTl; int k0;
            if (u < 4)      { WTh = g_WsrcT_h; WTl = g_WsrcT_l; k0 = u*KC; }
            else if (u < 8) { WTh = g_WdstT_h; WTl = g_WdstT_l; k0 = (u-4)*KC; }
            else            { WTh = g_W2T_h;   WTl = g_W2T_l;   k0 = (u-8)*KC; }
            prefetchB(Bhb[p^1], Blb[p^1], WTh, WTl, k0, colbase, tid);
            if (u < 8) {
                int id = (u < 4) ? s_src[m] : s_dst[m];
                const float* rp = (id & 1 ? emb1 : emb0)
                                  + (size_t)(id >> 1)*EMB + (u & 3)*KC + half*16;
                loadV_row(v, rp);
            } else {
                int kb = (u - 8)*KC + half*16;
                #pragma unroll
                for (int j = 0; j < 16; j++)
                    v[j] = fmaxf(fmaf(ts, s_w1a[kb+j],
                                 fmaf(lw, s_w1b[kb+j], s_b1[kb+j])), 0.f);
            }
            cp_wait<1>();
        } else {
            cp_wait<0>();
        }
        __syncthreads();
        mma_chunk(Ah, Al, Bhb[p], Blb[p], acc, wm, wn, lane);
        __syncthreads();
        p ^= 1;
    }

    // --- epilogue: + relb2, relu, mask, fanout-mean via shfl ---
    #pragma unroll
    for (int mf = 0; mf < 2; mf++) {
        int r0 = wm*32 + mf*16 + (lane >> 2);
        int r1 = r0 + 8;
        float v0 = s_val[r0], v1 = s_val[r1];
        int rel0 = s_rel[r0], rel1 = s_rel[r1];
        int brow = blockIdx.x*8 + wm*2 + mf;
        #pragma unroll
        for (int nf = 0; nf < 8; nf++) {
            int cl = wn*64 + nf*8 + 2*(lane & 3);
            int gc = colbase + cl;
            float p0 = fmaxf(acc[mf][nf][0] + g_relb2[rel0*HID + gc],     0.f)*v0
                     + fmaxf(acc[mf][nf][2] + g_relb2[rel1*HID + gc],     0.f)*v1;
            float p1 = fmaxf(acc[mf][nf][1] + g_relb2[rel0*HID + gc + 1], 0.f)*v0
                     + fmaxf(acc[mf][nf][3] + g_relb2[rel1*HID + gc + 1], 0.f)*v1;
            p0 += __shfl_xor_sync(0xffffffffu, p0, 4);
            p0 += __shfl_xor_sync(0xffffffffu, p0, 8);
            p0 += __shfl_xor_sync(0xffffffffu, p0, 16);
            p1 += __shfl_xor_sync(0xffffffffu, p1, 4);
            p1 += __shfl_xor_sync(0xffffffffu, p1, 8);
            p1 += __shfl_xor_sync(0xffffffffu, p1, 16);
            if ((lane >> 2) == 0) {
                *(float2*)&g_neigh[(size_t)brow*HID + gc] =
                    make_float2(p0 * 0.0625f, p1 * 0.0625f);
            }
        }
    }
}

// ------------------------------------------------------------------
// output kernel
// ------------------------------------------------------------------
__global__ __launch_bounds__(256, 2)
void out_kernel(const int* __restrict__ node_ids,
                const float* __restrict__ emb0,
                float* __restrict__ out) {
    extern __shared__ float smem[];
    float* Ah = smem;
    float* Al = Ah + BM*AP;
    float* Bhb[2] = { Al + BM*AP,            Al + BM*AP + 2*KC*BP };
    float* Blb[2] = { Al + BM*AP + KC*BP,    Al + BM*AP + 3*KC*BP };

    __shared__ int s_id[BM];

    int tid  = threadIdx.x;
    int lane = tid & 31;
    int w    = tid >> 5;
    int wm   = w & 3, wn = w >> 2;
    int colbase = blockIdx.y * BN;
    int rowbase = blockIdx.x * BM;
    int m = tid >> 1, half = tid & 1;

    if (tid < BM) s_id[tid] = node_ids[rowbase + tid];

    prefetchB(Bhb[0], Blb[0], g_WselfT_h, g_WselfT_l, 0, colbase, tid);
    __syncthreads();

    float acc[2][8][4];
    #pragma unroll
    for (int a = 0; a < 2; a++)
        #pragma unroll
        for (int b = 0; b < 8; b++)
            #pragma unroll
            for (int q = 0; q < 4; q++) acc[a][b][q] = 0.f;

    float v[16];
    loadV_row(v, emb0 + (size_t)s_id[m]*EMB + half*16);

    int p = 0;
    #pragma unroll 1
    for (int t = 0; t < 12; t++) {
        stageA_vals(Ah, Al, v, m, half);
        if (t < 11) {
            int u = t + 1;
            const float *WTh, *WTl; int k0;
            if (u < 4) { WTh = g_WselfT_h;  WTl = g_WselfT_l;  k0 = u*KC; }
            else       { WTh = g_WneighT_h; WTl = g_WneighT_l; k0 = (u-4)*KC; }
            prefetchB(Bhb[p^1], Blb[p^1], WTh, WTl, k0, colbase, tid);
            if (u < 4) {
                loadV_row(v, emb0 + (size_t)s_id[m]*EMB + u*KC + half*16);
            } else {
                loadV_row(v, g_neigh + (size_t)(rowbase + m)*HID + (u-4)*KC + half*16);
            }
            cp_wait<1>();
        } else {
            cp_wait<0>();
        }
        __syncthreads();
        mma_chunk(Ah, Al, Bhb[p], Blb[p], acc, wm, wn, lane);
        __syncthreads();
        p ^= 1;
    }

    #pragma unroll
    for (int mf = 0; mf < 2; mf++) {
        int r0 = rowbase + wm*32 + mf*16 + (lane >> 2);
        int r1 = r0 + 8;
        #pragma unroll
        for (int nf = 0; nf < 8; nf++) {
            int gc = colbase + wn*64 + nf*8 + 2*(lane & 3);
            *(float2*)&out[(size_t)r0*HID + gc] =
                make_float2(fmaxf(acc[mf][nf][0], 0.f), fmaxf(acc[mf][nf][1], 0.f));
            *(float2*)&out[(size_t)r1*HID + gc] =
                make_float2(fmaxf(acc[mf][nf][2], 0.f), fmaxf(acc[mf][nf][3], 0.f));
        }
    }
}

// ------------------------------------------------------------------
extern "C" void kernel_launch(void* const* d_in, const int* in_sizes, int n_in,
                              void* d_out, int out_size) {
    const int*   node_ids = (const int*)d_in[0];
    const int*   nbr_ev   = (const int*)d_in[1];
    const int*   ev_st    = (const int*)d_in[2];
    const int*   ev_dt    = (const int*)d_in[3];
    const int*   ev_et    = (const int*)d_in[4];
    const int*   ev_sid   = (const int*)d_in[5];
    const int*   ev_did   = (const int*)d_in[6];
    const int*   ev_ts    = (const int*)d_in[7];
    const float* ev_w     = (const float*)d_in[8];
    const float* emb0     = (const float*)d_in[9];
    const float* emb1     = (const float*)d_in[10];
    const float* edge_emb = (const float*)d_in[11];
    const float* edge_lin = (const float*)d_in[12];
    const float* mlp_w1   = (const float*)d_in[13];
    const float* mlp_b1   = (const float*)d_in[14];
    const float* mlp_w2   = (const float*)d_in[15];
    const float* mlp_b2   = (const float*)d_in[16];
    const float* wsrc     = (const float*)d_in[17];
    const float* wdst     = (const float*)d_in[18];
    const float* wself    = (const float*)d_in[19];
    const float* wneigh   = (const float*)d_in[20];
    float* out = (float*)d_out;

    size_t smem_dyn = (size_t)DYN_FLOATS * sizeof(float);
    cudaFuncSetAttribute(ev_kernel,  cudaFuncAttributeMaxDynamicSharedMemorySize, (int)smem_dyn);
    cudaFuncSetAttribute(out_kernel, cudaFuncAttributeMaxDynamicSharedMemorySize, (int)smem_dyn);

    prep_split<<<(HID*HID + 255)/256, 256>>>(wsrc, wdst, mlp_w2, wself, wneigh);
    prep_relb2<<<1, 256>>>(edge_emb, edge_lin, mlp_b2);

    dim3 gev(BE/BM, 2);
    ev_kernel<<<gev, 256, smem_dyn>>>(nbr_ev, ev_st, ev_dt, ev_et, ev_sid, ev_did,
                                      ev_ts, ev_w, emb0, emb1, mlp_w1, mlp_b1);
    dim3 gout(NB/BM, 2);
    out_kernel<<<gout, 256, smem_dyn>>>(node_ids, emb0, out);
}

// round 6
// speedup vs baseline: 1.0207x; 1.0207x over previous
#include <cuda_runtime.h>
#include <math.h>
#include <stdint.h>

#define NB      16384
#define FANOUT  16
#define BE      (NB*FANOUT)
#define EMB     128
#define HID     256
#define NEDGE   16

#define BM      128
#define BN      128
#define KC      32
#define AP      36        // A smem pitch: banks (4q+c) conflict-free
#define BP      136       // B smem pitch: banks (8c+q) perm of 0..31 -> conflict-free

// ---- persistent scratch ----
__device__ float g_WsrcT_h[EMB*HID],  g_WsrcT_l[EMB*HID];
__device__ float g_WdstT_h[EMB*HID],  g_WdstT_l[EMB*HID];
__device__ float g_WselfT_h[EMB*HID], g_WselfT_l[EMB*HID];
__device__ float g_W2T_h[HID*HID],    g_W2T_l[HID*HID];
__device__ float g_WneighT_h[HID*HID],g_WneighT_l[HID*HID];
__device__ float g_relb2[NEDGE*HID];
__device__ float g_neigh[(size_t)NB*HID];

// ------------------------------------------------------------------
__device__ __forceinline__ float tf32_rna(float x) {
    uint32_t r;
    asm("cvt.rna.tf32.f32 %0, %1;" : "=r"(r) : "f"(x));
    return __uint_as_float(r);
}
__device__ __forceinline__ void split2(float x, float& h, float& l) {
    h = tf32_rna(x);
    l = tf32_rna(x - h);
}
__device__ __forceinline__ void mma8(float* d, const float* a, const float* b) {
    asm volatile("mma.sync.aligned.m16n8k8.row.col.f32.tf32.tf32.f32 "
        "{%0,%1,%2,%3},{%4,%5,%6,%7},{%8,%9},{%0,%1,%2,%3};"
        : "+f"(d[0]), "+f"(d[1]), "+f"(d[2]), "+f"(d[3])
        : "r"(__float_as_uint(a[0])), "r"(__float_as_uint(a[1])),
          "r"(__float_as_uint(a[2])), "r"(__float_as_uint(a[3])),
          "r"(__float_as_uint(b[0])), "r"(__float_as_uint(b[1])));
}
template<int N> __device__ __forceinline__ void cp_wait() {
    asm volatile("cp.async.wait_group %0;" :: "n"(N));
}
__device__ __forceinline__ void cp16(void* dst, const void* src) {
    uint32_t sa = (uint32_t)__cvta_generic_to_shared(dst);
    asm volatile("cp.async.ca.shared.global [%0], [%1], 16;" :: "r"(sa), "l"(src));
}

// ------------------------------------------------------------------
// prep: transpose + hi/lo split of weights into [K][N] layout
// ------------------------------------------------------------------
__global__ void prep_split(const float* __restrict__ Wsrc, const float* __restrict__ Wdst,
                           const float* __restrict__ W2,   const float* __restrict__ Wself,
                           const float* __restrict__ Wneigh) {
    int i = blockIdx.x * blockDim.x + threadIdx.x;
    if (i < EMB*HID) {
        int k = i / HID, n = i % HID;
        float h, l;
        split2(Wsrc [n*EMB + k], h, l); g_WsrcT_h [i] = h; g_WsrcT_l [i] = l;
        split2(Wdst [n*EMB + k], h, l); g_WdstT_h [i] = h; g_WdstT_l [i] = l;
        split2(Wself[n*EMB + k], h, l); g_WselfT_h[i] = h; g_WselfT_l[i] = l;
    }
    if (i < HID*HID) {
        int k = i / HID, n = i % HID;
        float h, l;
        split2(W2    [n*HID + k], h, l); g_W2T_h    [i] = h; g_W2T_l    [i] = l;
        split2(Wneigh[n*HID + k], h, l); g_WneighT_h[i] = h; g_WneighT_l[i] = l;
    }
}

__global__ void prep_relb2(const float* __restrict__ edge_emb,
                           const float* __restrict__ edge_lin_w,
                           const float* __restrict__ b2) {
    int n = threadIdx.x;
    for (int r = 0; r < NEDGE; r++) {
        float s = b2[n];
        #pragma unroll 4
        for (int k = 0; k < EMB; k++)
            s = fmaf(edge_emb[r*EMB + k], edge_lin_w[n*EMB + k], s);
        g_relb2[r*HID + n] = s;
    }
}

// ------------------------------------------------------------------
// producers
// ------------------------------------------------------------------
// async prefetch of one KC x BN weight chunk (hi+lo) into smem
__device__ __forceinline__ void prefetchB(float* Bh, float* Bl,
                                          const float* __restrict__ WTh,
                                          const float* __restrict__ WTl,
                                          int k0, int colbase, int tid) {
    int k  = tid >> 3;                // 0..31
    int n0 = (tid & 7) << 4;          // 0,16,...,112
    const float* sh = WTh + (size_t)(k0 + k)*HID + colbase + n0;
    const float* sl = WTl + (size_t)(k0 + k)*HID + colbase + n0;
    float* dh = Bh + k*BP + n0;
    float* dl = Bl + k*BP + n0;
    #pragma unroll
    for (int j = 0; j < 4; j++) {
        cp16(dh + 4*j, sh + 4*j);
        cp16(dl + 4*j, sl + 4*j);
    }
    asm volatile("cp.async.commit_group;");
}

// split v[16] and store into A tile (thread covers row m, k-range half*16..+15)
__device__ __forceinline__ void stageA_vals(float* Ah, float* Al,
                                            const float* v, int m, int half) {
    float* dh = Ah + m*AP + half*16;
    float* dl = Al + m*AP + half*16;
    #pragma unroll
    for (int j = 0; j < 4; j++) {
        float4 h, l;
        split2(v[4*j+0], h.x, l.x); split2(v[4*j+1], h.y, l.y);
        split2(v[4*j+2], h.z, l.z); split2(v[4*j+3], h.w, l.w);
        *(float4*)(dh + 4*j) = h;
        *(float4*)(dl + 4*j) = l;
    }
}

__device__ __forceinline__ void loadV_row(float* v, const float* rowPtr) {
    #pragma unroll
    for (int j = 0; j < 4; j++) {
        float4 t = ((const float4*)rowPtr)[j];
        v[4*j] = t.x; v[4*j+1] = t.y; v[4*j+2] = t.z; v[4*j+3] = t.w;
    }
}

// ------------------------------------------------------------------
// warp mma over one KC=32 chunk; 3xTF32 compensated (R3-proven layout)
// ------------------------------------------------------------------
__device__ __forceinline__ void mma_chunk(const float* __restrict__ Ah,
                                          const float* __restrict__ Al,
                                          const float* __restrict__ Bh,
                                          const float* __restrict__ Bl,
                                          float (&acc)[2][8][4],
                                          int wm, int wn, int lane) {
    int r0 = wm*32 + (lane >> 2);
    int c  = lane & 3;
    int nb = wn*64 + (lane >> 2);
    #pragma unroll
    for (int kk = 0; kk < KC; kk += 8) {
        float ah[2][4], al[2][4];
        #pragma unroll
        for (int mf = 0; mf < 2; mf++) {
            const float* ph = Ah + (r0 + mf*16)*AP + kk + c;
            ah[mf][0] = ph[0];      ah[mf][1] = ph[8*AP];
            ah[mf][2] = ph[4];      ah[mf][3] = ph[8*AP + 4];
            const float* pl = Al + (r0 + mf*16)*AP + kk + c;
            al[mf][0] = pl[0];      al[mf][1] = pl[8*AP];
            al[mf][2] = pl[4];      al[mf][3] = pl[8*AP + 4];
        }
        #pragma unroll
        for (int nf = 0; nf < 8; nf++) {
            const float* pb = Bh + (kk + c)*BP + nb + nf*8;
            float bh[2] = { pb[0], pb[4*BP] };
            const float* pl2 = Bl + (kk + c)*BP + nb + nf*8;
            float bl[2] = { pl2[0], pl2[4*BP] };
            #pragma unroll
            for (int mf = 0; mf < 2; mf++) {
                mma8(acc[mf][nf], ah[mf], bh);
                mma8(acc[mf][nf], al[mf], bh);
                mma8(acc[mf][nf], ah[mf], bl);
            }
        }
    }
}

#define DYN_FLOATS (2*BM*AP + 4*KC*BP)   // 9216 + 17408 = 26624 floats

// ------------------------------------------------------------------
// event kernel
// ------------------------------------------------------------------
__global__ __launch_bounds__(256, 2)
void ev_kernel(const int* __restrict__ nbr_ev,
               const int* __restrict__ ev_st, const int* __restrict__ ev_dt,
               const int* __restrict__ ev_et,
               const int* __restrict__ ev_sid, const int* __restrict__ ev_did,
               const int* __restrict__ ev_ts,  const float* __restrict__ ev_w,
               const float* __restrict__ emb0, const float* __restrict__ emb1,
               const float* __restrict__ mlp_w1, const float* __restrict__ mlp_b1) {
    extern __shared__ float smem[];
    float* Ah = smem;
    float* Al = Ah + BM*AP;
    float* Bhb[2] = { Al + BM*AP,            Al + BM*AP + 2*KC*BP };
    float* Blb[2] = { Al + BM*AP + KC*BP,    Al + BM*AP + 3*KC*BP };

    __shared__ int   s_src[BM], s_dst[BM];   // (id<<1)|type
    __shared__ float s_ts[BM], s_lw[BM], s_val[BM];
    __shared__ int   s_rel[BM];
    __shared__ float s_w1a[HID], s_w1b[HID], s_b1[HID];

    int tid  = threadIdx.x;
    int lane = tid & 31;
    int w    = tid >> 5;
    int wm   = w & 3, wn = w >> 2;
    int colbase = blockIdx.y * BN;
    int m = tid >> 1, half = tid & 1;

    if (tid < BM) {
        int ev = nbr_ev[blockIdx.x*BM + tid];
        int e  = ev < 0 ? 0 : ev;
        s_val[tid] = ev < 0 ? 0.f : 1.f;
        s_src[tid] = (ev_sid[e] << 1) | (ev_st[e] != 0);
        s_dst[tid] = (ev_did[e] << 1) | (ev_dt[e] != 0);
        s_rel[tid] = ev_et[e];
        s_ts[tid]  = (float)ev_ts[e] / 1000000.0f;
        s_lw[tid]  = log1pf(ev_w[e]);
    }
    s_w1a[tid] = mlp_w1[tid*2 + 0];
    s_w1b[tid] = mlp_w1[tid*2 + 1];
    s_b1[tid]  = mlp_b1[tid];

    prefetchB(Bhb[0], Blb[0], g_WsrcT_h, g_WsrcT_l, 0, colbase, tid);
    __syncthreads();

    float ts = s_ts[m], lw = s_lw[m];
    // hoist row pointers for this thread's A row
    const float* srcRow = ((s_src[m] & 1) ? emb1 : emb0) + (size_t)(s_src[m] >> 1)*EMB;
    const float* dstRow = ((s_dst[m] & 1) ? emb1 : emb0) + (size_t)(s_dst[m] >> 1)*EMB;

    float acc[2][8][4];
    #pragma unroll
    for (int a = 0; a < 2; a++)
        #pragma unroll
        for (int b = 0; b < 8; b++)
            #pragma unroll
            for (int q = 0; q < 4; q++) acc[a][b][q] = 0.f;

    // v(0): src embedding, chunk 0
    float v[16];
    loadV_row(v, srcRow + half*16);

    int p = 0;
    #pragma unroll 1
    for (int t = 0; t < 16; t++) {
        stageA_vals(Ah, Al, v, m, half);
        if (t < 15) {
            int u = t + 1;
            const float *WTh, *WTl; int k0;
            if (u < 4)      { WTh = g_WsrcT_h; WTl = g_WsrcT_l; k0 = u*KC; }
            else if (u < 8) { WTh = g_WdstT_h; WTl = g_WdstT_l; k0 = (u-4)*KC; }
            else            { WTh = g_W2T_h;   WTl = g_W2T_l;   k0 = (u-8)*KC; }
            prefetchB(Bhb[p^1], Blb[p^1], WTh, WTl, k0, colbase, tid);
            if (u < 8) {
                const float* rp = (u < 4 ? srcRow : dstRow) + (u & 3)*KC + half*16;
                loadV_row(v, rp);
            } else {
                int kb = (u - 8)*KC + half*16;
                #pragma unroll
                for (int j = 0; j < 16; j++)
                    v[j] = fmaxf(fmaf(ts, s_w1a[kb+j],
                                 fmaf(lw, s_w1b[kb+j], s_b1[kb+j])), 0.f);
            }
            cp_wait<1>();
        } else {
            cp_wait<0>();
        }
        __syncthreads();
        mma_chunk(Ah, Al, Bhb[p], Blb[p], acc, wm, wn, lane);
        __syncthreads();
        p ^= 1;
    }

    // --- epilogue: + relb2, relu, mask, fanout-mean via shfl ---
    #pragma unroll
    for (int mf = 0; mf < 2; mf++) {
        int r0 = wm*32 + mf*16 + (lane >> 2);
        int r1 = r0 + 8;
        float v0 = s_val[r0], v1 = s_val[r1];
        int rel0 = s_rel[r0], rel1 = s_rel[r1];
        int brow = blockIdx.x*8 + wm*2 + mf;
        #pragma unroll
        for (int nf = 0; nf < 8; nf++) {
            int cl = wn*64 + nf*8 + 2*(lane & 3);
            int gc = colbase + cl;
            float p0 = fmaxf(acc[mf][nf][0] + g_relb2[rel0*HID + gc],     0.f)*v0
                     + fmaxf(acc[mf][nf][2] + g_relb2[rel1*HID + gc],     0.f)*v1;
            float p1 = fmaxf(acc[mf][nf][1] + g_relb2[rel0*HID + gc + 1], 0.f)*v0
                     + fmaxf(acc[mf][nf][3] + g_relb2[rel1*HID + gc + 1], 0.f)*v1;
            p0 += __shfl_xor_sync(0xffffffffu, p0, 4);
            p0 += __shfl_xor_sync(0xffffffffu, p0, 8);
            p0 += __shfl_xor_sync(0xffffffffu, p0, 16);
            p1 += __shfl_xor_sync(0xffffffffu, p1, 4);
            p1 += __shfl_xor_sync(0xffffffffu, p1, 8);
            p1 += __shfl_xor_sync(0xffffffffu, p1, 16);
            if ((lane >> 2) == 0) {
                *(float2*)&g_neigh[(size_t)brow*HID + gc] =
                    make_float2(p0 * 0.0625f, p1 * 0.0625f);
            }
        }
    }
}

// ------------------------------------------------------------------
// output kernel
// ------------------------------------------------------------------
__global__ __launch_bounds__(256, 2)
void out_kernel(const int* __restrict__ node_ids,
                const float* __restrict__ emb0,
                float* __restrict__ out) {
    extern __shared__ float smem[];
    float* Ah = smem;
    float* Al = Ah + BM*AP;
    float* Bhb[2] = { Al + BM*AP,            Al + BM*AP + 2*KC*BP };
    float* Blb[2] = { Al + BM*AP + KC*BP,    Al + BM*AP + 3*KC*BP };

    __shared__ int s_id[BM];

    int tid  = threadIdx.x;
    int lane = tid & 31;
    int w    = tid >> 5;
    int wm   = w & 3, wn = w >> 2;
    int colbase = blockIdx.y * BN;
    int rowbase = blockIdx.x * BM;
    int m = tid >> 1, half = tid & 1;

    if (tid < BM) s_id[tid] = node_ids[rowbase + tid];

    prefetchB(Bhb[0], Blb[0], g_WselfT_h, g_WselfT_l, 0, colbase, tid);
    __syncthreads();

    const float* selfRow  = emb0 + (size_t)s_id[m]*EMB;
    const float* neighRow = g_neigh + (size_t)(rowbase + m)*HID;

    float acc[2][8][4];
    #pragma unroll
    for (int a = 0; a < 2; a++)
        #pragma unroll
        for (int b = 0; b < 8; b++)
            #pragma unroll
            for (int q = 0; q < 4; q++) acc[a][b][q] = 0.f;

    float v[16];
    loadV_row(v, selfRow + half*16);

    int p = 0;
    #pragma unroll 1
    for (int t = 0; t < 12; t++) {
        stageA_vals(Ah, Al, v, m, half);
        if (t < 11) {
            int u = t + 1;
            const float *WTh, *WTl; int k0;
            if (u < 4) { WTh = g_WselfT_h;  WTl = g_WselfT_l;  k0 = u*KC; }
            else       { WTh = g_WneighT_h; WTl = g_WneighT_l; k0 = (u-4)*KC; }
            prefetchB(Bhb[p^1], Blb[p^1], WTh, WTl, k0, colbase, tid);
            if (u < 4) loadV_row(v, selfRow + u*KC + half*16);
            else       loadV_row(v, neighRow + (u-4)*KC + half*16);
            cp_wait<1>();
        } else {
            cp_wait<0>();
        }
        __syncthreads();
        mma_chunk(Ah, Al, Bhb[p], Blb[p], acc, wm, wn, lane);
        __syncthreads();
        p ^= 1;
    }

    #pragma unroll
    for (int mf = 0; mf < 2; mf++) {
        int r0 = rowbase + wm*32 + mf*16 + (lane >> 2);
        int r1 = r0 + 8;
        #pragma unroll
        for (int nf = 0; nf < 8; nf++) {
            int gc = colbase + wn*64 + nf*8 + 2*(lane & 3);
            *(float2*)&out[(size_t)r0*HID + gc] =
                make_float2(fmaxf(acc[mf][nf][0], 0.f), fmaxf(acc[mf][nf][1], 0.f));
            *(float2*)&out[(size_t)r1*HID + gc] =
                make_float2(fmaxf(acc[mf][nf][2], 0.f), fmaxf(acc[mf][nf][3], 0.f));
        }
    }
}

// ------------------------------------------------------------------
extern "C" void kernel_launch(void* const* d_in, const int* in_sizes, int n_in,
                              void* d_out, int out_size) {
    const int*   node_ids = (const int*)d_in[0];
    const int*   nbr_ev   = (const int*)d_in[1];
    const int*   ev_st    = (const int*)d_in[2];
    const int*   ev_dt    = (const int*)d_in[3];
    const int*   ev_et    = (const int*)d_in[4];
    const int*   ev_sid   = (const int*)d_in[5];
    const int*   ev_did   = (const int*)d_in[6];
    const int*   ev_ts    = (const int*)d_in[7];
    const float* ev_w     = (const float*)d_in[8];
    const float* emb0     = (const float*)d_in[9];
    const float* emb1     = (const float*)d_in[10];
    const float* edge_emb = (const float*)d_in[11];
    const float* edge_lin = (const float*)d_in[12];
    const float* mlp_w1   = (const float*)d_in[13];
    const float* mlp_b1   = (const float*)d_in[14];
    const float* mlp_w2   = (const float*)d_in[15];
    const float* mlp_b2   = (const float*)d_in[16];
    const float* wsrc     = (const float*)d_in[17];
    const float* wdst     = (const float*)d_in[18];
    const float* wself    = (const float*)d_in[19];
    const float* wneigh   = (const float*)d_in[20];
    float* out = (float*)d_out;

    size_t smem_dyn = (size_t)DYN_FLOATS * sizeof(float);
    cudaFuncSetAttribute(ev_kernel,  cudaFuncAttributeMaxDynamicSharedMemorySize, (int)smem_dyn);
    cudaFuncSetAttribute(out_kernel, cudaFuncAttributeMaxDynamicSharedMemorySize, (int)smem_dyn);

    prep_split<<<(HID*HID + 255)/256, 256>>>(wsrc, wdst, mlp_w2, wself, wneigh);
    prep_relb2<<<1, 256>>>(edge_emb, edge_lin, mlp_b2);

    dim3 gev(BE/BM, 2);
    ev_kernel<<<gev, 256, smem_dyn>>>(nbr_ev, ev_st, ev_dt, ev_et, ev_sid, ev_did,
                                      ev_ts, ev_w, emb0, emb1, mlp_w1, mlp_b1);
    dim3 gout(NB/BM, 2);
    out_kernel<<<gout, 256, smem_dyn>>>(node_ids, emb0, out);
}

// round 7
// speedup vs baseline: 1.7517x; 1.7161x over previous
#include <cuda_runtime.h>
#include <cuda_bf16.h>
#include <math.h>
#include <stdint.h>

#define NB      16384
#define FANOUT  16
#define BE      (NB*FANOUT)
#define EMB     128
#define HID     256
#define NEDGE   16

#define BM      128
#define BN      128
#define KC      32        // k per chunk
#define K2C     16        // packed k-pairs per chunk
#define AP2     20        // A smem pitch (uint32): 20*dq+dc never 0 mod 32 -> conflict-free
#define BP2     136       // B smem pitch (uint32): 136 mod 32 = 8 -> conflict-free

// ---- persistent scratch: packed bf16x2 weights, [k2][n] layout ----
__device__ uint32_t g_Wsrc_h [EMB/2*HID], g_Wsrc_l [EMB/2*HID];
__device__ uint32_t g_Wdst_h [EMB/2*HID], g_Wdst_l [EMB/2*HID];
__device__ uint32_t g_Wself_h[EMB/2*HID], g_Wself_l[EMB/2*HID];
__device__ uint32_t g_W2_h   [HID/2*HID], g_W2_l   [HID/2*HID];
__device__ uint32_t g_Wng_h  [HID/2*HID], g_Wng_l  [HID/2*HID];
__device__ float    g_relb2[NEDGE*HID];
__device__ float    g_neigh[(size_t)NB*HID];

// ------------------------------------------------------------------
__device__ __forceinline__ void splitb(float x, __nv_bfloat16& h, __nv_bfloat16& l) {
    h = __float2bfloat16_rn(x);
    l = __float2bfloat16_rn(x - __bfloat162float(h));
}
__device__ __forceinline__ uint32_t packb(__nv_bfloat16 a, __nv_bfloat16 b) {
    __nv_bfloat162 t; t.x = a; t.y = b;          // .x = low 16 bits = even k
    return *reinterpret_cast<uint32_t*>(&t);
}
// split two consecutive values into packed hi / lo words
__device__ __forceinline__ void split_pack2(float x0, float x1,
                                            uint32_t& hi, uint32_t& lo) {
    __nv_bfloat16 h0, l0, h1, l1;
    splitb(x0, h0, l0); splitb(x1, h1, l1);
    hi = packb(h0, h1); lo = packb(l0, l1);
}
__device__ __forceinline__ void mma16(float* d, const uint32_t* a, const uint32_t* b) {
    asm volatile("mma.sync.aligned.m16n8k16.row.col.f32.bf16.bf16.f32 "
        "{%0,%1,%2,%3},{%4,%5,%6,%7},{%8,%9},{%0,%1,%2,%3};"
        : "+f"(d[0]), "+f"(d[1]), "+f"(d[2]), "+f"(d[3])
        : "r"(a[0]), "r"(a[1]), "r"(a[2]), "r"(a[3]), "r"(b[0]), "r"(b[1]));
}

// ------------------------------------------------------------------
// prep: transpose + bf16 hi/lo split + pack weights into [k2][n] uint32
// ------------------------------------------------------------------
__device__ __forceinline__ void pack_w(const float* __restrict__ W, uint32_t* outh,
                                       uint32_t* outl, int K, int i) {
    int k2 = i / HID, n = i % HID;
    uint32_t hi, lo;
    split_pack2(W[n*K + 2*k2], W[n*K + 2*k2 + 1], hi, lo);
    outh[i] = hi; outl[i] = lo;
}
__global__ void prep_split(const float* __restrict__ Wsrc, const float* __restrict__ Wdst,
                           const float* __restrict__ W2,   const float* __restrict__ Wself,
                           const float* __restrict__ Wneigh) {
    int i = blockIdx.x * blockDim.x + threadIdx.x;
    if (i < EMB/2*HID) {
        pack_w(Wsrc,  g_Wsrc_h,  g_Wsrc_l,  EMB, i);
        pack_w(Wdst,  g_Wdst_h,  g_Wdst_l,  EMB, i);
        pack_w(Wself, g_Wself_h, g_Wself_l, EMB, i);
    }
    if (i < HID/2*HID) {
        pack_w(W2,     g_W2_h,  g_W2_l,  HID, i);
        pack_w(Wneigh, g_Wng_h, g_Wng_l, HID, i);
    }
}

__global__ void prep_relb2(const float* __restrict__ edge_emb,
                           const float* __restrict__ edge_lin_w,
                           const float* __restrict__ b2) {
    int n = threadIdx.x;
    for (int r = 0; r < NEDGE; r++) {
        float s = b2[n];
        #pragma unroll 4
        for (int k = 0; k < EMB; k++)
            s = fmaf(edge_emb[r*EMB + k], edge_lin_w[n*EMB + k], s);
        g_relb2[r*HID + n] = s;
    }
}

// ------------------------------------------------------------------
// producers (synchronous, R3-proven structure)
// ------------------------------------------------------------------
// copy one K2C x BN packed weight chunk (hi+lo) into smem
__device__ __forceinline__ void stageB(uint32_t* Bh, uint32_t* Bl,
                                       const uint32_t* __restrict__ Wh,
                                       const uint32_t* __restrict__ Wl,
                                       int k20, int colbase, int tid) {
    int k  = tid >> 4;                 // 0..15
    int n0 = (tid & 15) << 3;          // 0,8,...,120
    const uint4* sh = (const uint4*)(Wh + (size_t)(k20 + k)*HID + colbase + n0);
    const uint4* sl = (const uint4*)(Wl + (size_t)(k20 + k)*HID + colbase + n0);
    uint4* dh = (uint4*)(Bh + k*BP2 + n0);
    uint4* dl = (uint4*)(Bl + k*BP2 + n0);
    dh[0] = sh[0]; dh[1] = sh[1];
    dl[0] = sl[0]; dl[1] = sl[1];
}

// split v[16] (fp32) into packed bf16 hi/lo and store into A tile
// thread covers row m, k-range half*16..+15 (k2 range half*8..+7)
__device__ __forceinline__ void stageA_vals(uint32_t* Ah, uint32_t* Al,
                                            const float* v, int m, int half) {
    uint32_t hb[8], lb[8];
    #pragma unroll
    for (int j = 0; j < 8; j++)
        split_pack2(v[2*j], v[2*j + 1], hb[j], lb[j]);
    uint4* dh = (uint4*)(Ah + m*AP2 + half*8);
    uint4* dl = (uint4*)(Al + m*AP2 + half*8);
    dh[0] = make_uint4(hb[0], hb[1], hb[2], hb[3]);
    dh[1] = make_uint4(hb[4], hb[5], hb[6], hb[7]);
    dl[0] = make_uint4(lb[0], lb[1], lb[2], lb[3]);
    dl[1] = make_uint4(lb[4], lb[5], lb[6], lb[7]);
}

__device__ __forceinline__ void loadV_row(float* v, const float* rowPtr) {
    #pragma unroll
    for (int j = 0; j < 4; j++) {
        float4 t = ((const float4*)rowPtr)[j];
        v[4*j] = t.x; v[4*j+1] = t.y; v[4*j+2] = t.z; v[4*j+3] = t.w;
    }
}

// ------------------------------------------------------------------
// warp mma over one KC=32 chunk; 2-term bf16 split (hh + hl + lh)
// ------------------------------------------------------------------
__device__ __forceinline__ void mma_chunk(const uint32_t* __restrict__ Ah,
                                          const uint32_t* __restrict__ Al,
                                          const uint32_t* __restrict__ Bh,
                                          const uint32_t* __restrict__ Bl,
                                          float (&acc)[2][8][4],
                                          int wm, int wn, int lane) {
    int q = lane >> 2, c = lane & 3;
    #pragma unroll
    for (int ks = 0; ks < 2; ks++) {
        int k2b = ks*8;
        uint32_t ah[2][4], al[2][4];
        #pragma unroll
        for (int mf = 0; mf < 2; mf++) {
            int r = wm*32 + mf*16 + q;
            const uint32_t* ph = Ah + r*AP2 + k2b + c;
            ah[mf][0] = ph[0];        ah[mf][1] = ph[8*AP2];
            ah[mf][2] = ph[4];        ah[mf][3] = ph[8*AP2 + 4];
            const uint32_t* pl = Al + r*AP2 + k2b + c;
            al[mf][0] = pl[0];        al[mf][1] = pl[8*AP2];
            al[mf][2] = pl[4];        al[mf][3] = pl[8*AP2 + 4];
        }
        #pragma unroll
        for (int nf = 0; nf < 8; nf++) {
            int n = wn*64 + nf*8 + q;
            const uint32_t* pb = Bh + (k2b + c)*BP2 + n;
            uint32_t bh[2] = { pb[0], pb[4*BP2] };
            const uint32_t* pb2 = Bl + (k2b + c)*BP2 + n;
            uint32_t bl[2] = { pb2[0], pb2[4*BP2] };
            #pragma unroll
            for (int mf = 0; mf < 2; mf++) {
                mma16(acc[mf][nf], ah[mf], bh);
                mma16(acc[mf][nf], ah[mf], bl);
                mma16(acc[mf][nf], al[mf], bh);
            }
        }
    }
}

#define DYN_U32 (2*BM*AP2 + 2*K2C*BP2)   // 5120 + 4352 = 9472 u32 = 37888 B

// ------------------------------------------------------------------
// event kernel
// ------------------------------------------------------------------
__global__ __launch_bounds__(256, 2)
void ev_kernel(const int* __restrict__ nbr_ev,
               const int* __restrict__ ev_st, const int* __restrict__ ev_dt,
               const int* __restrict__ ev_et,
               const int* __restrict__ ev_sid, const int* __restrict__ ev_did,
               const int* __restrict__ ev_ts,  const float* __restrict__ ev_w,
               const float* __restrict__ emb0, const float* __restrict__ emb1,
               const float* __restrict__ mlp_w1, const float* __restrict__ mlp_b1) {
    extern __shared__ uint32_t smem[];
    uint32_t* Ah = smem;                    // BM*AP2
    uint32_t* Al = Ah + BM*AP2;
    uint32_t* Bh = Al + BM*AP2;             // K2C*BP2
    uint32_t* Bl = Bh + K2C*BP2;

    __shared__ int   s_src[BM], s_dst[BM];  // (id<<1)|type
    __shared__ float s_ts[BM], s_lw[BM], s_val[BM];
    __shared__ int   s_rel[BM];
    __shared__ float s_w1a[HID], s_w1b[HID], s_b1[HID];

    int tid  = threadIdx.x;
    int lane = tid & 31;
    int w    = tid >> 5;
    int wm   = w & 3, wn = w >> 2;
    int colbase = blockIdx.y * BN;
    int m = tid >> 1, half = tid & 1;

    if (tid < BM) {
        int ev = nbr_ev[blockIdx.x*BM + tid];
        int e  = ev < 0 ? 0 : ev;
        s_val[tid] = ev < 0 ? 0.f : 1.f;
        s_src[tid] = (ev_sid[e] << 1) | (ev_st[e] != 0);
        s_dst[tid] = (ev_did[e] << 1) | (ev_dt[e] != 0);
        s_rel[tid] = ev_et[e];
        s_ts[tid]  = (float)ev_ts[e] / 1000000.0f;
        s_lw[tid]  = log1pf(ev_w[e]);
    }
    s_w1a[tid] = mlp_w1[tid*2 + 0];
    s_w1b[tid] = mlp_w1[tid*2 + 1];
    s_b1[tid]  = mlp_b1[tid];
    __syncthreads();

    float ts = s_ts[m], lw = s_lw[m];
    const float* srcRow = ((s_src[m] & 1) ? emb1 : emb0) + (size_t)(s_src[m] >> 1)*EMB;
    const float* dstRow = ((s_dst[m] & 1) ? emb1 : emb0) + (size_t)(s_dst[m] >> 1)*EMB;

    float acc[2][8][4];
    #pragma unroll
    for (int a = 0; a < 2; a++)
        #pragma unroll
        for (int b = 0; b < 8; b++)
            #pragma unroll
            for (int q = 0; q < 4; q++) acc[a][b][q] = 0.f;

    #pragma unroll 1
    for (int t = 0; t < 16; t++) {
        // --- stage A chunk t ---
        float v[16];
        if (t < 8) {
            const float* rp = (t < 4 ? srcRow : dstRow) + (t & 3)*KC + half*16;
            loadV_row(v, rp);
        } else {
            int kb = (t - 8)*KC + half*16;
            #pragma unroll
            for (int j = 0; j < 16; j++)
                v[j] = fmaxf(fmaf(ts, s_w1a[kb+j],
                             fmaf(lw, s_w1b[kb+j], s_b1[kb+j])), 0.f);
        }
        stageA_vals(Ah, Al, v, m, half);
        // --- stage B chunk t ---
        {
            const uint32_t *Wh, *Wl; int k20;
            if (t < 4)      { Wh = g_Wsrc_h; Wl = g_Wsrc_l; k20 = t*K2C; }
            else if (t < 8) { Wh = g_Wdst_h; Wl = g_Wdst_l; k20 = (t-4)*K2C; }
            else            { Wh = g_W2_h;   Wl = g_W2_l;   k20 = (t-8)*K2C; }
            stageB(Bh, Bl, Wh, Wl, k20, colbase, tid);
        }
        __syncthreads();
        mma_chunk(Ah, Al, Bh, Bl, acc, wm, wn, lane);
        __syncthreads();
    }

    // --- epilogue: + relb2, relu, mask, fanout-mean via shfl ---
    #pragma unroll
    for (int mf = 0; mf < 2; mf++) {
        int r0 = wm*32 + mf*16 + (lane >> 2);
        int r1 = r0 + 8;
        float v0 = s_val[r0], v1 = s_val[r1];
        int rel0 = s_rel[r0], rel1 = s_rel[r1];
        int brow = blockIdx.x*8 + wm*2 + mf;
        #pragma unroll
        for (int nf = 0; nf < 8; nf++) {
            int cl = wn*64 + nf*8 + 2*(lane & 3);
            int gc = colbase + cl;
            float p0 = fmaxf(acc[mf][nf][0] + g_relb2[rel0*HID + gc],     0.f)*v0
                     + fmaxf(acc[mf][nf][2] + g_relb2[rel1*HID + gc],     0.f)*v1;
            float p1 = fmaxf(acc[mf][nf][1] + g_relb2[rel0*HID + gc + 1], 0.f)*v0
                     + fmaxf(acc[mf][nf][3] + g_relb2[rel1*HID + gc + 1], 0.f)*v1;
            p0 += __shfl_xor_sync(0xffffffffu, p0, 4);
            p0 += __shfl_xor_sync(0xffffffffu, p0, 8);
            p0 += __shfl_xor_sync(0xffffffffu, p0, 16);
            p1 += __shfl_xor_sync(0xffffffffu, p1, 4);
            p1 += __shfl_xor_sync(0xffffffffu, p1, 8);
            p1 += __shfl_xor_sync(0xffffffffu, p1, 16);
            if ((lane >> 2) == 0) {
                *(float2*)&g_neigh[(size_t)brow*HID + gc] =
                    make_float2(p0 * 0.0625f, p1 * 0.0625f);
            }
        }
    }
}

// ------------------------------------------------------------------
// output kernel: out = relu(self@WselfT + neigh@WneighT)
// ------------------------------------------------------------------
__global__ __launch_bounds__(256, 2)
void out_kernel(const int* __restrict__ node_ids,
                const float* __restrict__ emb0,
                float* __restrict__ out) {
    extern __shared__ uint32_t smem[];
    uint32_t* Ah = smem;
    uint32_t* Al = Ah + BM*AP2;
    uint32_t* Bh = Al + BM*AP2;
    uint32_t* Bl = Bh + K2C*BP2;

    __shared__ int s_id[BM];

    int tid  = threadIdx.x;
    int lane = tid & 31;
    int w    = tid >> 5;
    int wm   = w & 3, wn = w >> 2;
    int colbase = blockIdx.y * BN;
    int rowbase = blockIdx.x * BM;
    int m = tid >> 1, half = tid & 1;

    if (tid < BM) s_id[tid] = node_ids[rowbase + tid];
    __syncthreads();

    const float* selfRow  = emb0 + (size_t)s_id[m]*EMB;
    const float* neighRow = g_neigh + (size_t)(rowbase + m)*HID;

    float acc[2][8][4];
    #pragma unroll
    for (int a = 0; a < 2; a++)
        #pragma unroll
        for (int b = 0; b < 8; b++)
            #pragma unroll
            for (int q = 0; q < 4; q++) acc[a][b][q] = 0.f;

    #pragma unroll 1
    for (int t = 0; t < 12; t++) {
        float v[16];
        if (t < 4) loadV_row(v, selfRow + t*KC + half*16);
        else       loadV_row(v, neighRow + (t-4)*KC + half*16);
        stageA_vals(Ah, Al, v, m, half);
        {
            const uint32_t *Wh, *Wl; int k20;
            if (t < 4) { Wh = g_Wself_h; Wl = g_Wself_l; k20 = t*K2C; }
            else       { Wh = g_Wng_h;   Wl = g_Wng_l;   k20 = (t-4)*K2C; }
            stageB(Bh, Bl, Wh, Wl, k20, colbase, tid);
        }
        __syncthreads();
        mma_chunk(Ah, Al, Bh, Bl, acc, wm, wn, lane);
        __syncthreads();
    }

    #pragma unroll
    for (int mf = 0; mf < 2; mf++) {
        int r0 = rowbase + wm*32 + mf*16 + (lane >> 2);
        int r1 = r0 + 8;
        #pragma unroll
        for (int nf = 0; nf < 8; nf++) {
            int gc = colbase + wn*64 + nf*8 + 2*(lane & 3);
            *(float2*)&out[(size_t)r0*HID + gc] =
                make_float2(fmaxf(acc[mf][nf][0], 0.f), fmaxf(acc[mf][nf][1], 0.f));
            *(float2*)&out[(size_t)r1*HID + gc] =
                make_float2(fmaxf(acc[mf][nf][2], 0.f), fmaxf(acc[mf][nf][3], 0.f));
        }
    }
}

// ------------------------------------------------------------------
extern "C" void kernel_launch(void* const* d_in, const int* in_sizes, int n_in,
                              void* d_out, int out_size) {
    const int*   node_ids = (const int*)d_in[0];
    const int*   nbr_ev   = (const int*)d_in[1];
    const int*   ev_st    = (const int*)d_in[2];
    const int*   ev_dt    = (const int*)d_in[3];
    const int*   ev_et    = (const int*)d_in[4];
    const int*   ev_sid   = (const int*)d_in[5];
    const int*   ev_did   = (const int*)d_in[6];
    const int*   ev_ts    = (const int*)d_in[7];
    const float* ev_w     = (const float*)d_in[8];
    const float* emb0     = (const float*)d_in[9];
    const float* emb1     = (const float*)d_in[10];
    const float* edge_emb = (const float*)d_in[11];
    const float* edge_lin = (const float*)d_in[12];
    const float* mlp_w1   = (const float*)d_in[13];
    const float* mlp_b1   = (const float*)d_in[14];
    const float* mlp_w2   = (const float*)d_in[15];
    const float* mlp_b2   = (const float*)d_in[16];
    const float* wsrc     = (const float*)d_in[17];
    const float* wdst     = (const float*)d_in[18];
    const float* wself    = (const float*)d_in[19];
    const float* wneigh   = (const float*)d_in[20];
    float* out = (float*)d_out;

    size_t smem_dyn = (size_t)DYN_U32 * sizeof(uint32_t);
    cudaFuncSetAttribute(ev_kernel,  cudaFuncAttributeMaxDynamicSharedMemorySize, (int)smem_dyn);
    cudaFuncSetAttribute(out_kernel, cudaFuncAttributeMaxDynamicSharedMemorySize, (int)smem_dyn);

    prep_split<<<(HID/2*HID + 255)/256, 256>>>(wsrc, wdst, mlp_w2, wself, wneigh);
    prep_relb2<<<1, 256>>>(edge_emb, edge_lin, mlp_b2);

    dim3 gev(BE/BM, 2);
    ev_kernel<<<gev, 256, smem_dyn>>>(nbr_ev, ev_st, ev_dt, ev_et, ev_sid, ev_did,
                                      ev_ts, ev_w, emb0, emb1, mlp_w1, mlp_b1);
    dim3 gout(NB/BM, 2);
    out_kernel<<<gout, 256, smem_dyn>>>(node_ids, emb0, out);
}

// round 8
// speedup vs baseline: 1.7531x; 1.0008x over previous
#include <cuda_runtime.h>
#include <cuda_bf16.h>
#include <math.h>
#include <stdint.h>

#define NB      16384
#define FANOUT  16
#define BE      (NB*FANOUT)
#define EMB     128
#define HID     256
#define NEDGE   16

#define BM      128
#define BN      128
#define KC      32        // k per chunk
#define K2C     16        // packed k-pairs per chunk
#define AP2     20        // A smem pitch (uint32): 20*dq+dc never 0 mod 32 -> conflict-free
#define BP2     136       // B smem pitch (uint32): 136 mod 32 = 8 -> conflict-free

// ---- persistent scratch: packed bf16x2 weights, [k2][n] layout ----
__device__ uint32_t g_Wsrc_h [EMB/2*HID], g_Wsrc_l [EMB/2*HID];
__device__ uint32_t g_Wdst_h [EMB/2*HID], g_Wdst_l [EMB/2*HID];
__device__ uint32_t g_Wself_h[EMB/2*HID], g_Wself_l[EMB/2*HID];
__device__ uint32_t g_W2_h   [HID/2*HID], g_W2_l   [HID/2*HID];
__device__ uint32_t g_Wng_h  [HID/2*HID], g_Wng_l  [HID/2*HID];
__device__ float    g_relb2[NEDGE*HID];
__device__ float    g_neigh[(size_t)NB*HID];

// ------------------------------------------------------------------
__device__ __forceinline__ void splitb(float x, __nv_bfloat16& h, __nv_bfloat16& l) {
    h = __float2bfloat16_rn(x);
    l = __float2bfloat16_rn(x - __bfloat162float(h));
}
__device__ __forceinline__ uint32_t packb(__nv_bfloat16 a, __nv_bfloat16 b) {
    __nv_bfloat162 t; t.x = a; t.y = b;          // .x = low 16 bits = even k
    return *reinterpret_cast<uint32_t*>(&t);
}
// split two consecutive values into packed hi / lo words
__device__ __forceinline__ void split_pack2(float x0, float x1,
                                            uint32_t& hi, uint32_t& lo) {
    __nv_bfloat16 h0, l0, h1, l1;
    splitb(x0, h0, l0); splitb(x1, h1, l1);
    hi = packb(h0, h1); lo = packb(l0, l1);
}
__device__ __forceinline__ void mma16(float* d, const uint32_t* a, const uint32_t* b) {
    asm volatile("mma.sync.aligned.m16n8k16.row.col.f32.bf16.bf16.f32 "
        "{%0,%1,%2,%3},{%4,%5,%6,%7},{%8,%9},{%0,%1,%2,%3};"
        : "+f"(d[0]), "+f"(d[1]), "+f"(d[2]), "+f"(d[3])
        : "r"(a[0]), "r"(a[1]), "r"(a[2]), "r"(a[3]), "r"(b[0]), "r"(b[1]));
}

// ------------------------------------------------------------------
// prep: transpose + bf16 hi/lo split + pack weights into [k2][n] uint32
// ------------------------------------------------------------------
__device__ __forceinline__ void pack_w(const float* __restrict__ W, uint32_t* outh,
                                       uint32_t* outl, int K, int i) {
    int k2 = i / HID, n = i % HID;
    uint32_t hi, lo;
    split_pack2(W[n*K + 2*k2], W[n*K + 2*k2 + 1], hi, lo);
    outh[i] = hi; outl[i] = lo;
}
__global__ void prep_split(const float* __restrict__ Wsrc, const float* __restrict__ Wdst,
                           const float* __restrict__ W2,   const float* __restrict__ Wself,
                           const float* __restrict__ Wneigh) {
    int i = blockIdx.x * blockDim.x + threadIdx.x;
    if (i < EMB/2*HID) {
        pack_w(Wsrc,  g_Wsrc_h,  g_Wsrc_l,  EMB, i);
        pack_w(Wdst,  g_Wdst_h,  g_Wdst_l,  EMB, i);
        pack_w(Wself, g_Wself_h, g_Wself_l, EMB, i);
    }
    if (i < HID/2*HID) {
        pack_w(W2,     g_W2_h,  g_W2_l,  HID, i);
        pack_w(Wneigh, g_Wng_h, g_Wng_l, HID, i);
    }
}

__global__ void prep_relb2(const float* __restrict__ edge_emb,
                           const float* __restrict__ edge_lin_w,
                           const float* __restrict__ b2) {
    int n = threadIdx.x;
    for (int r = 0; r < NEDGE; r++) {
        float s = b2[n];
        #pragma unroll 4
        for (int k = 0; k < EMB; k++)
            s = fmaf(edge_emb[r*EMB + k], edge_lin_w[n*EMB + k], s);
        g_relb2[r*HID + n] = s;
    }
}

// ------------------------------------------------------------------
// producers (synchronous, R3-proven structure)
// ------------------------------------------------------------------
// copy one K2C x BN packed weight chunk (hi+lo) into smem
__device__ __forceinline__ void stageB(uint32_t* Bh, uint32_t* Bl,
                                       const uint32_t* __restrict__ Wh,
                                       const uint32_t* __restrict__ Wl,
                                       int k20, int colbase, int tid) {
    int k  = tid >> 4;                 // 0..15
    int n0 = (tid & 15) << 3;          // 0,8,...,120
    const uint4* sh = (const uint4*)(Wh + (size_t)(k20 + k)*HID + colbase + n0);
    const uint4* sl = (const uint4*)(Wl + (size_t)(k20 + k)*HID + colbase + n0);
    uint4* dh = (uint4*)(Bh + k*BP2 + n0);
    uint4* dl = (uint4*)(Bl + k*BP2 + n0);
    dh[0] = sh[0]; dh[1] = sh[1];
    dl[0] = sl[0]; dl[1] = sl[1];
}

// split v[16] (fp32) into packed bf16 hi/lo and store into A tile
// thread covers row m, k-range half*16..+15 (k2 range half*8..+7)
__device__ __forceinline__ void stageA_vals(uint32_t* Ah, uint32_t* Al,
                                            const float* v, int m, int half) {
    uint32_t hb[8], lb[8];
    #pragma unroll
    for (int j = 0; j < 8; j++)
        split_pack2(v[2*j], v[2*j + 1], hb[j], lb[j]);
    uint4* dh = (uint4*)(Ah + m*AP2 + half*8);
    uint4* dl = (uint4*)(Al + m*AP2 + half*8);
    dh[0] = make_uint4(hb[0], hb[1], hb[2], hb[3]);
    dh[1] = make_uint4(hb[4], hb[5], hb[6], hb[7]);
    dl[0] = make_uint4(lb[0], lb[1], lb[2], lb[3]);
    dl[1] = make_uint4(lb[4], lb[5], lb[6], lb[7]);
}

__device__ __forceinline__ void loadV_row(float* v, const float* rowPtr) {
    #pragma unroll
    for (int j = 0; j < 4; j++) {
        float4 t = ((const float4*)rowPtr)[j];
        v[4*j] = t.x; v[4*j+1] = t.y; v[4*j+2] = t.z; v[4*j+3] = t.w;
    }
}

// ------------------------------------------------------------------
// warp mma over one KC=32 chunk; 2-term bf16 split (hh + hl + lh)
// ------------------------------------------------------------------
__device__ __forceinline__ void mma_chunk(const uint32_t* __restrict__ Ah,
                                          const uint32_t* __restrict__ Al,
                                          const uint32_t* __restrict__ Bh,
                                          const uint32_t* __restrict__ Bl,
                                          float (&acc)[2][8][4],
                                          int wm, int wn, int lane) {
    int q = lane >> 2, c = lane & 3;
    #pragma unroll
    for (int ks = 0; ks < 2; ks++) {
        int k2b = ks*8;
        uint32_t ah[2][4], al[2][4];
        #pragma unroll
        for (int mf = 0; mf < 2; mf++) {
            int r = wm*32 + mf*16 + q;
            const uint32_t* ph = Ah + r*AP2 + k2b + c;
            ah[mf][0] = ph[0];        ah[mf][1] = ph[8*AP2];
            ah[mf][2] = ph[4];        ah[mf][3] = ph[8*AP2 + 4];
            const uint32_t* pl = Al + r*AP2 + k2b + c;
            al[mf][0] = pl[0];        al[mf][1] = pl[8*AP2];
            al[mf][2] = pl[4];        al[mf][3] = pl[8*AP2 + 4];
        }
        #pragma unroll
        for (int nf = 0; nf < 8; nf++) {
            int n = wn*64 + nf*8 + q;
            const uint32_t* pb = Bh + (k2b + c)*BP2 + n;
            uint32_t bh[2] = { pb[0], pb[4*BP2] };
            const uint32_t* pb2 = Bl + (k2b + c)*BP2 + n;
            uint32_t bl[2] = { pb2[0], pb2[4*BP2] };
            #pragma unroll
            for (int mf = 0; mf < 2; mf++) {
                mma16(acc[mf][nf], ah[mf], bh);
                mma16(acc[mf][nf], ah[mf], bl);
                mma16(acc[mf][nf], al[mf], bh);
            }
        }
    }
}

#define DYN_U32 (2*BM*AP2 + 2*K2C*BP2)   // 5120 + 4352 = 9472 u32 = 37888 B

// ------------------------------------------------------------------
// event kernel
// ------------------------------------------------------------------
__global__ __launch_bounds__(256, 2)
void ev_kernel(const int* __restrict__ nbr_ev,
               const int* __restrict__ ev_st, const int* __restrict__ ev_dt,
               const int* __restrict__ ev_et,
               const int* __restrict__ ev_sid, const int* __restrict__ ev_did,
               const int* __restrict__ ev_ts,  const float* __restrict__ ev_w,
               const float* __restrict__ emb0, const float* __restrict__ emb1,
               const float* __restrict__ mlp_w1, const float* __restrict__ mlp_b1) {
    extern __shared__ uint32_t smem[];
    uint32_t* Ah = smem;                    // BM*AP2
    uint32_t* Al = Ah + BM*AP2;
    uint32_t* Bh = Al + BM*AP2;             // K2C*BP2
    uint32_t* Bl = Bh + K2C*BP2;

    __shared__ int   s_src[BM], s_dst[BM];  // (id<<1)|type
    __shared__ float s_ts[BM], s_lw[BM], s_val[BM];
    __shared__ int   s_rel[BM];
    __shared__ float s_w1a[HID], s_w1b[HID], s_b1[HID];

    int tid  = threadIdx.x;
    int lane = tid & 31;
    int w    = tid >> 5;
    int wm   = w & 3, wn = w >> 2;
    int colbase = blockIdx.y * BN;
    int m = tid >> 1, half = tid & 1;

    if (tid < BM) {
        int ev = nbr_ev[blockIdx.x*BM + tid];
        int e  = ev < 0 ? 0 : ev;
        s_val[tid] = ev < 0 ? 0.f : 1.f;
        s_src[tid] = (ev_sid[e] << 1) | (ev_st[e] != 0);
        s_dst[tid] = (ev_did[e] << 1) | (ev_dt[e] != 0);
        s_rel[tid] = ev_et[e];
        s_ts[tid]  = (float)ev_ts[e] / 1000000.0f;
        s_lw[tid]  = log1pf(ev_w[e]);
    }
    s_w1a[tid] = mlp_w1[tid*2 + 0];
    s_w1b[tid] = mlp_w1[tid*2 + 1];
    s_b1[tid]  = mlp_b1[tid];
    __syncthreads();

    float ts = s_ts[m], lw = s_lw[m];
    const float* srcRow = ((s_src[m] & 1) ? emb1 : emb0) + (size_t)(s_src[m] >> 1)*EMB;
    const float* dstRow = ((s_dst[m] & 1) ? emb1 : emb0) + (size_t)(s_dst[m] >> 1)*EMB;

    float acc[2][8][4];
    #pragma unroll
    for (int a = 0; a < 2; a++)
        #pragma unroll
        for (int b = 0; b < 8; b++)
            #pragma unroll
            for (int q = 0; q < 4; q++) acc[a][b][q] = 0.f;

    #pragma unroll 1
    for (int t = 0; t < 16; t++) {
        // --- stage A chunk t ---
        float v[16];
        if (t < 8) {
            const float* rp = (t < 4 ? srcRow : dstRow) + (t & 3)*KC + half*16;
            loadV_row(v, rp);
        } else {
            int kb = (t - 8)*KC + half*16;
            #pragma unroll
            for (int j = 0; j < 16; j++)
                v[j] = fmaxf(fmaf(ts, s_w1a[kb+j],
                             fmaf(lw, s_w1b[kb+j], s_b1[kb+j])), 0.f);
        }
        stageA_vals(Ah, Al, v, m, half);
        // --- stage B chunk t ---
        {
            const uint32_t *Wh, *Wl; int k20;
            if (t < 4)      { Wh = g_Wsrc_h; Wl = g_Wsrc_l; k20 = t*K2C; }
            else if (t < 8) { Wh = g_Wdst_h; Wl = g_Wdst_l; k20 = (t-4)*K2C; }
            else            { Wh = g_W2_h;   Wl = g_W2_l;   k20 = (t-8)*K2C; }
            stageB(Bh, Bl, Wh, Wl, k20, colbase, tid);
        }
        __syncthreads();
        mma_chunk(Ah, Al, Bh, Bl, acc, wm, wn, lane);
        __syncthreads();
    }

    // --- epilogue: + relb2, relu, mask, fanout-mean via shfl ---
    #pragma unroll
    for (int mf = 0; mf < 2; mf++) {
        int r0 = wm*32 + mf*16 + (lane >> 2);
        int r1 = r0 + 8;
        float v0 = s_val[r0], v1 = s_val[r1];
        int rel0 = s_rel[r0], rel1 = s_rel[r1];
        int brow = blockIdx.x*8 + wm*2 + mf;
        #pragma unroll
        for (int nf = 0; nf < 8; nf++) {
            int cl = wn*64 + nf*8 + 2*(lane & 3);
            int gc = colbase + cl;
            float p0 = fmaxf(acc[mf][nf][0] + g_relb2[rel0*HID + gc],     0.f)*v0
                     + fmaxf(acc[mf][nf][2] + g_relb2[rel1*HID + gc],     0.f)*v1;
            float p1 = fmaxf(acc[mf][nf][1] + g_relb2[rel0*HID + gc + 1], 0.f)*v0
                     + fmaxf(acc[mf][nf][3] + g_relb2[rel1*HID + gc + 1], 0.f)*v1;
            p0 += __shfl_xor_sync(0xffffffffu, p0, 4);
            p0 += __shfl_xor_sync(0xffffffffu, p0, 8);
            p0 += __shfl_xor_sync(0xffffffffu, p0, 16);
            p1 += __shfl_xor_sync(0xffffffffu, p1, 4);
            p1 += __shfl_xor_sync(0xffffffffu, p1, 8);
            p1 += __shfl_xor_sync(0xffffffffu, p1, 16);
            if ((lane >> 2) == 0) {
                *(float2*)&g_neigh[(size_t)brow*HID + gc] =
                    make_float2(p0 * 0.0625f, p1 * 0.0625f);
            }
        }
    }
}

// ------------------------------------------------------------------
// output kernel: out = relu(self@WselfT + neigh@WneighT)
// ------------------------------------------------------------------
__global__ __launch_bounds__(256, 2)
void out_kernel(const int* __restrict__ node_ids,
                const float* __restrict__ emb0,
                float* __restrict__ out) {
    extern __shared__ uint32_t smem[];
    uint32_t* Ah = smem;
    uint32_t* Al = Ah + BM*AP2;
    uint32_t* Bh = Al + BM*AP2;
    uint32_t* Bl = Bh + K2C*BP2;

    __shared__ int s_id[BM];

    int tid  = threadIdx.x;
    int lane = tid & 31;
    int w    = tid >> 5;
    int wm   = w & 3, wn = w >> 2;
    int colbase = blockIdx.y * BN;
    int rowbase = blockIdx.x * BM;
    int m = tid >> 1, half = tid & 1;

    if (tid < BM) s_id[tid] = node_ids[rowbase + tid];
    __syncthreads();

    const float* selfRow  = emb0 + (size_t)s_id[m]*EMB;
    const float* neighRow = g_neigh + (size_t)(rowbase + m)*HID;

    float acc[2][8][4];
    #pragma unroll
    for (int a = 0; a < 2; a++)
        #pragma unroll
        for (int b = 0; b < 8; b++)
            #pragma unroll
            for (int q = 0; q < 4; q++) acc[a][b][q] = 0.f;

    #pragma unroll 1
    for (int t = 0; t < 12; t++) {
        float v[16];
        if (t < 4) loadV_row(v, selfRow + t*KC + half*16);
        else       loadV_row(v, neighRow + (t-4)*KC + half*16);
        stageA_vals(Ah, Al, v, m, half);
        {
            const uint32_t *Wh, *Wl; int k20;
            if (t < 4) { Wh = g_Wself_h; Wl = g_Wself_l; k20 = t*K2C; }
            else       { Wh = g_Wng_h;   Wl = g_Wng_l;   k20 = (t-4)*K2C; }
            stageB(Bh, Bl, Wh, Wl, k20, colbase, tid);
        }
        __syncthreads();
        mma_chunk(Ah, Al, Bh, Bl, acc, wm, wn, lane);
        __syncthreads();
    }

    #pragma unroll
    for (int mf = 0; mf < 2; mf++) {
        int r0 = rowbase + wm*32 + mf*16 + (lane >> 2);
        int r1 = r0 + 8;
        #pragma unroll
        for (int nf = 0; nf < 8; nf++) {
            int gc = colbase + wn*64 + nf*8 + 2*(lane & 3);
            *(float2*)&out[(size_t)r0*HID + gc] =
                make_float2(fmaxf(acc[mf][nf][0], 0.f), fmaxf(acc[mf][nf][1], 0.f));
            *(float2*)&out[(size_t)r1*HID + gc] =
                make_float2(fmaxf(acc[mf][nf][2], 0.f), fmaxf(acc[mf][nf][3], 0.f));
        }
    }
}

// ------------------------------------------------------------------
extern "C" void kernel_launch(void* const* d_in, const int* in_sizes, int n_in,
                              void* d_out, int out_size) {
    const int*   node_ids = (const int*)d_in[0];
    const int*   nbr_ev   = (const int*)d_in[1];
    const int*   ev_st    = (const int*)d_in[2];
    const int*   ev_dt    = (const int*)d_in[3];
    const int*   ev_et    = (const int*)d_in[4];
    const int*   ev_sid   = (const int*)d_in[5];
    const int*   ev_did   = (const int*)d_in[6];
    const int*   ev_ts    = (const int*)d_in[7];
    const float* ev_w     = (const float*)d_in[8];
    const float* emb0     = (const float*)d_in[9];
    const float* emb1     = (const float*)d_in[10];
    const float* edge_emb = (const float*)d_in[11];
    const float* edge_lin = (const float*)d_in[12];
    const float* mlp_w1   = (const float*)d_in[13];
    const float* mlp_b1   = (const float*)d_in[14];
    const float* mlp_w2   = (const float*)d_in[15];
    const float* mlp_b2   = (const float*)d_in[16];
    const float* wsrc     = (const float*)d_in[17];
    const float* wdst     = (const float*)d_in[18];
    const float* wself    = (const float*)d_in[19];
    const float* wneigh   = (const float*)d_in[20];
    float* out = (float*)d_out;

    size_t smem_dyn = (size_t)DYN_U32 * sizeof(uint32_t);
    cudaFuncSetAttribute(ev_kernel,  cudaFuncAttributeMaxDynamicSharedMemorySize, (int)smem_dyn);
    cudaFuncSetAttribute(out_kernel, cudaFuncAttributeMaxDynamicSharedMemorySize, (int)smem_dyn);

    prep_split<<<(HID/2*HID + 255)/256, 256>>>(wsrc, wdst, mlp_w2, wself, wneigh);
    prep_relb2<<<1, 256>>>(edge_emb, edge_lin, mlp_b2);

    dim3 gev(BE/BM, 2);
    ev_kernel<<<gev, 256, smem_dyn>>>(nbr_ev, ev_st, ev_dt, ev_et, ev_sid, ev_did,
                                      ev_ts, ev_w, emb0, emb1, mlp_w1, mlp_b1);
    dim3 gout(NB/BM, 2);
    out_kernel<<<gout, 256, smem_dyn>>>(node_ids, emb0, out);
}

// round 9
// speedup vs baseline: 1.7547x; 1.0009x over previous
#include <cuda_runtime.h>
#include <cuda_bf16.h>
#include <math.h>
#include <stdint.h>

#define NB      16384
#define FANOUT  16
#define BE      (NB*FANOUT)
#define EMB     128
#define HID     256
#define NEDGE   16

#define BM      128
#define BN      128
#define KC      32        // k per chunk
#define K2C     16        // packed k-pairs per chunk
#define AP2     20        // A smem pitch (uint32): 20*dq+dc never 0 mod 32 -> conflict-free
#define BP2     136       // B smem pitch (uint32): 136 mod 32 = 8 -> conflict-free

// ---- persistent scratch: packed bf16x2 weights, [k2][n] layout ----
__device__ uint32_t g_Wsrc_h [EMB/2*HID], g_Wsrc_l [EMB/2*HID];
__device__ uint32_t g_Wdst_h [EMB/2*HID], g_Wdst_l [EMB/2*HID];
__device__ uint32_t g_Wself_h[EMB/2*HID], g_Wself_l[EMB/2*HID];
__device__ uint32_t g_W2_h   [HID/2*HID], g_W2_l   [HID/2*HID];
__device__ uint32_t g_Wng_h  [HID/2*HID], g_Wng_l  [HID/2*HID];
__device__ float    g_relb2[NEDGE*HID];
__device__ float    g_neigh[(size_t)NB*HID];

// ------------------------------------------------------------------
__device__ __forceinline__ void splitb(float x, __nv_bfloat16& h, __nv_bfloat16& l) {
    h = __float2bfloat16_rn(x);
    l = __float2bfloat16_rn(x - __bfloat162float(h));
}
__device__ __forceinline__ uint32_t packb(__nv_bfloat16 a, __nv_bfloat16 b) {
    __nv_bfloat162 t; t.x = a; t.y = b;          // .x = low 16 bits = even k
    return *reinterpret_cast<uint32_t*>(&t);
}
// split two consecutive values into packed hi / lo words
__device__ __forceinline__ void split_pack2(float x0, float x1,
                                            uint32_t& hi, uint32_t& lo) {
    __nv_bfloat16 h0, l0, h1, l1;
    splitb(x0, h0, l0); splitb(x1, h1, l1);
    hi = packb(h0, h1); lo = packb(l0, l1);
}
__device__ __forceinline__ void mma16(float* d, const uint32_t* a, const uint32_t* b) {
    asm volatile("mma.sync.aligned.m16n8k16.row.col.f32.bf16.bf16.f32 "
        "{%0,%1,%2,%3},{%4,%5,%6,%7},{%8,%9},{%0,%1,%2,%3};"
        : "+f"(d[0]), "+f"(d[1]), "+f"(d[2]), "+f"(d[3])
        : "r"(a[0]), "r"(a[1]), "r"(a[2]), "r"(a[3]), "r"(b[0]), "r"(b[1]));
}

// ------------------------------------------------------------------
// prep: transpose + bf16 hi/lo split + pack weights into [k2][n] uint32
// ------------------------------------------------------------------
__device__ __forceinline__ void pack_w(const float* __restrict__ W, uint32_t* outh,
                                       uint32_t* outl, int K, int i) {
    int k2 = i / HID, n = i % HID;
    uint32_t hi, lo;
    split_pack2(W[n*K + 2*k2], W[n*K + 2*k2 + 1], hi, lo);
    outh[i] = hi; outl[i] = lo;
}
__global__ void prep_split(const float* __restrict__ Wsrc, const float* __restrict__ Wdst,
                           const float* __restrict__ W2,   const float* __restrict__ Wself,
                           const float* __restrict__ Wneigh) {
    int i = blockIdx.x * blockDim.x + threadIdx.x;
    if (i < EMB/2*HID) {
        pack_w(Wsrc,  g_Wsrc_h,  g_Wsrc_l,  EMB, i);
        pack_w(Wdst,  g_Wdst_h,  g_Wdst_l,  EMB, i);
        pack_w(Wself, g_Wself_h, g_Wself_l, EMB, i);
    }
    if (i < HID/2*HID) {
        pack_w(W2,     g_W2_h,  g_W2_l,  HID, i);
        pack_w(Wneigh, g_Wng_h, g_Wng_l, HID, i);
    }
}

__global__ void prep_relb2(const float* __restrict__ edge_emb,
                           const float* __restrict__ edge_lin_w,
                           const float* __restrict__ b2) {
    int n = threadIdx.x;
    for (int r = 0; r < NEDGE; r++) {
        float s = b2[n];
        #pragma unroll 4
        for (int k = 0; k < EMB; k++)
            s = fmaf(edge_emb[r*EMB + k], edge_lin_w[n*EMB + k], s);
        g_relb2[r*HID + n] = s;
    }
}

// ------------------------------------------------------------------
// producers (synchronous, R3-proven structure)
// ------------------------------------------------------------------
// copy one K2C x BN packed weight chunk (hi+lo) into smem
__device__ __forceinline__ void stageB(uint32_t* Bh, uint32_t* Bl,
                                       const uint32_t* __restrict__ Wh,
                                       const uint32_t* __restrict__ Wl,
                                       int k20, int colbase, int tid) {
    int k  = tid >> 4;                 // 0..15
    int n0 = (tid & 15) << 3;          // 0,8,...,120
    const uint4* sh = (const uint4*)(Wh + (size_t)(k20 + k)*HID + colbase + n0);
    const uint4* sl = (const uint4*)(Wl + (size_t)(k20 + k)*HID + colbase + n0);
    uint4* dh = (uint4*)(Bh + k*BP2 + n0);
    uint4* dl = (uint4*)(Bl + k*BP2 + n0);
    dh[0] = sh[0]; dh[1] = sh[1];
    dl[0] = sl[0]; dl[1] = sl[1];
}

// split v[16] (fp32) into packed bf16 hi/lo and store into A tile
// thread covers row m, k-range half*16..+15 (k2 range half*8..+7)
__device__ __forceinline__ void stageA_vals(uint32_t* Ah, uint32_t* Al,
                                            const float* v, int m, int half) {
    uint32_t hb[8], lb[8];
    #pragma unroll
    for (int j = 0; j < 8; j++)
        split_pack2(v[2*j], v[2*j + 1], hb[j], lb[j]);
    uint4* dh = (uint4*)(Ah + m*AP2 + half*8);
    uint4* dl = (uint4*)(Al + m*AP2 + half*8);
    dh[0] = make_uint4(hb[0], hb[1], hb[2], hb[3]);
    dh[1] = make_uint4(hb[4], hb[5], hb[6], hb[7]);
    dl[0] = make_uint4(lb[0], lb[1], lb[2], lb[3]);
    dl[1] = make_uint4(lb[4], lb[5], lb[6], lb[7]);
}

__device__ __forceinline__ void loadV_row(float* v, const float* rowPtr) {
    #pragma unroll
    for (int j = 0; j < 4; j++) {
        float4 t = ((const float4*)rowPtr)[j];
        v[4*j] = t.x; v[4*j+1] = t.y; v[4*j+2] = t.z; v[4*j+3] = t.w;
    }
}

// ------------------------------------------------------------------
// warp mma over one KC=32 chunk; 2-term bf16 split (hh + hl + lh)
// ------------------------------------------------------------------
__device__ __forceinline__ void mma_chunk(const uint32_t* __restrict__ Ah,
                                          const uint32_t* __restrict__ Al,
                                          const uint32_t* __restrict__ Bh,
                                          const uint32_t* __restrict__ Bl,
                                          float (&acc)[2][8][4],
                                          int wm, int wn, int lane) {
    int q = lane >> 2, c = lane & 3;
    #pragma unroll
    for (int ks = 0; ks < 2; ks++) {
        int k2b = ks*8;
        uint32_t ah[2][4], al[2][4];
        #pragma unroll
        for (int mf = 0; mf < 2; mf++) {
            int r = wm*32 + mf*16 + q;
            const uint32_t* ph = Ah + r*AP2 + k2b + c;
            ah[mf][0] = ph[0];        ah[mf][1] = ph[8*AP2];
            ah[mf][2] = ph[4];        ah[mf][3] = ph[8*AP2 + 4];
            const uint32_t* pl = Al + r*AP2 + k2b + c;
            al[mf][0] = pl[0];        al[mf][1] = pl[8*AP2];
            al[mf][2] = pl[4];        al[mf][3] = pl[8*AP2 + 4];
        }
        #pragma unroll
        for (int nf = 0; nf < 8; nf++) {
            int n = wn*64 + nf*8 + q;
            const uint32_t* pb = Bh + (k2b + c)*BP2 + n;
            uint32_t bh[2] = { pb[0], pb[4*BP2] };
            const uint32_t* pb2 = Bl + (k2b + c)*BP2 + n;
            uint32_t bl[2] = { pb2[0], pb2[4*BP2] };
            #pragma unroll
            for (int mf = 0; mf < 2; mf++) {
                mma16(acc[mf][nf], ah[mf], bh);
                mma16(acc[mf][nf], ah[mf], bl);
                mma16(acc[mf][nf], al[mf], bh);
            }
        }
    }
}

#define DYN_U32 (2*BM*AP2 + 2*K2C*BP2)   // 5120 + 4352 = 9472 u32 = 37888 B

// ------------------------------------------------------------------
// event kernel
// ------------------------------------------------------------------
__global__ __launch_bounds__(256, 2)
void ev_kernel(const int* __restrict__ nbr_ev,
               const int* __restrict__ ev_st, const int* __restrict__ ev_dt,
               const int* __restrict__ ev_et,
               const int* __restrict__ ev_sid, const int* __restrict__ ev_did,
               const int* __restrict__ ev_ts,  const float* __restrict__ ev_w,
               const float* __restrict__ emb0, const float* __restrict__ emb1,
               const float* __restrict__ mlp_w1, const float* __restrict__ mlp_b1) {
    extern __shared__ uint32_t smem[];
    uint32_t* Ah = smem;                    // BM*AP2
    uint32_t* Al = Ah + BM*AP2;
    uint32_t* Bh = Al + BM*AP2;             // K2C*BP2
    uint32_t* Bl = Bh + K2C*BP2;

    __shared__ int   s_src[BM], s_dst[BM];  // (id<<1)|type
    __shared__ float s_ts[BM], s_lw[BM], s_val[BM];
    __shared__ int   s_rel[BM];
    __shared__ float s_w1a[HID], s_w1b[HID], s_b1[HID];

    int tid  = threadIdx.x;
    int lane = tid & 31;
    int w    = tid >> 5;
    int wm   = w & 3, wn = w >> 2;
    int colbase = blockIdx.y * BN;
    int m = tid >> 1, half = tid & 1;

    if (tid < BM) {
        int ev = nbr_ev[blockIdx.x*BM + tid];
        int e  = ev < 0 ? 0 : ev;
        s_val[tid] = ev < 0 ? 0.f : 1.f;
        s_src[tid] = (ev_sid[e] << 1) | (ev_st[e] != 0);
        s_dst[tid] = (ev_did[e] << 1) | (ev_dt[e] != 0);
        s_rel[tid] = ev_et[e];
        s_ts[tid]  = (float)ev_ts[e] / 1000000.0f;
        s_lw[tid]  = log1pf(ev_w[e]);
    }
    s_w1a[tid] = mlp_w1[tid*2 + 0];
    s_w1b[tid] = mlp_w1[tid*2 + 1];
    s_b1[tid]  = mlp_b1[tid];
    __syncthreads();

    float ts = s_ts[m], lw = s_lw[m];
    const float* srcRow = ((s_src[m] & 1) ? emb1 : emb0) + (size_t)(s_src[m] >> 1)*EMB;
    const float* dstRow = ((s_dst[m] & 1) ? emb1 : emb0) + (size_t)(s_dst[m] >> 1)*EMB;

    float acc[2][8][4];
    #pragma unroll
    for (int a = 0; a < 2; a++)
        #pragma unroll
        for (int b = 0; b < 8; b++)
            #pragma unroll
            for (int q = 0; q < 4; q++) acc[a][b][q] = 0.f;

    #pragma unroll 1
    for (int t = 0; t < 16; t++) {
        // --- stage A chunk t ---
        float v[16];
        if (t < 8) {
            const float* rp = (t < 4 ? srcRow : dstRow) + (t & 3)*KC + half*16;
            loadV_row(v, rp);
        } else {
            int kb = (t - 8)*KC + half*16;
            #pragma unroll
            for (int j = 0; j < 16; j++)
                v[j] = fmaxf(fmaf(ts, s_w1a[kb+j],
                             fmaf(lw, s_w1b[kb+j], s_b1[kb+j])), 0.f);
        }
        stageA_vals(Ah, Al, v, m, half);
        // --- stage B chunk t ---
        {
            const uint32_t *Wh, *Wl; int k20;
            if (t < 4)      { Wh = g_Wsrc_h; Wl = g_Wsrc_l; k20 = t*K2C; }
            else if (t < 8) { Wh = g_Wdst_h; Wl = g_Wdst_l; k20 = (t-4)*K2C; }
            else            { Wh = g_W2_h;   Wl = g_W2_l;   k20 = (t-8)*K2C; }
            stageB(Bh, Bl, Wh, Wl, k20, colbase, tid);
        }
        __syncthreads();
        mma_chunk(Ah, Al, Bh, Bl, acc, wm, wn, lane);
        __syncthreads();
    }

    // --- epilogue: + relb2, relu, mask, fanout-mean via shfl ---
    #pragma unroll
    for (int mf = 0; mf < 2; mf++) {
        int r0 = wm*32 + mf*16 + (lane >> 2);
        int r1 = r0 + 8;
        float v0 = s_val[r0], v1 = s_val[r1];
        int rel0 = s_rel[r0], rel1 = s_rel[r1];
        int brow = blockIdx.x*8 + wm*2 + mf;
        #pragma unroll
        for (int nf = 0; nf < 8; nf++) {
            int cl = wn*64 + nf*8 + 2*(lane & 3);
            int gc = colbase + cl;
            float p0 = fmaxf(acc[mf][nf][0] + g_relb2[rel0*HID + gc],     0.f)*v0
                     + fmaxf(acc[mf][nf][2] + g_relb2[rel1*HID + gc],     0.f)*v1;
            float p1 = fmaxf(acc[mf][nf][1] + g_relb2[rel0*HID + gc + 1], 0.f)*v0
                     + fmaxf(acc[mf][nf][3] + g_relb2[rel1*HID + gc + 1], 0.f)*v1;
            p0 += __shfl_xor_sync(0xffffffffu, p0, 4);
            p0 += __shfl_xor_sync(0xffffffffu, p0, 8);
            p0 += __shfl_xor_sync(0xffffffffu, p0, 16);
            p1 += __shfl_xor_sync(0xffffffffu, p1, 4);
            p1 += __shfl_xor_sync(0xffffffffu, p1, 8);
            p1 += __shfl_xor_sync(0xffffffffu, p1, 16);
            if ((lane >> 2) == 0) {
                *(float2*)&g_neigh[(size_t)brow*HID + gc] =
                    make_float2(p0 * 0.0625f, p1 * 0.0625f);
            }
        }
    }
}

// ------------------------------------------------------------------
// output kernel: out = relu(self@WselfT + neigh@WneighT)
// ------------------------------------------------------------------
__global__ __launch_bounds__(256, 2)
void out_kernel(const int* __restrict__ node_ids,
                const float* __restrict__ emb0,
                float* __restrict__ out) {
    extern __shared__ uint32_t smem[];
    uint32_t* Ah = smem;
    uint32_t* Al = Ah + BM*AP2;
    uint32_t* Bh = Al + BM*AP2;
    uint32_t* Bl = Bh + K2C*BP2;

    __shared__ int s_id[BM];

    int tid  = threadIdx.x;
    int lane = tid & 31;
    int w    = tid >> 5;
    int wm   = w & 3, wn = w >> 2;
    int colbase = blockIdx.y * BN;
    int rowbase = blockIdx.x * BM;
    int m = tid >> 1, half = tid & 1;

    if (tid < BM) s_id[tid] = node_ids[rowbase + tid];
    __syncthreads();

    const float* selfRow  = emb0 + (size_t)s_id[m]*EMB;
    const float* neighRow = g_neigh + (size_t)(rowbase + m)*HID;

    float acc[2][8][4];
    #pragma unroll
    for (int a = 0; a < 2; a++)
        #pragma unroll
        for (int b = 0; b < 8; b++)
            #pragma unroll
            for (int q = 0; q < 4; q++) acc[a][b][q] = 0.f;

    #pragma unroll 1
    for (int t = 0; t < 12; t++) {
        float v[16];
        if (t < 4) loadV_row(v, selfRow + t*KC + half*16);
        else       loadV_row(v, neighRow + (t-4)*KC + half*16);
        stageA_vals(Ah, Al, v, m, half);
        {
            const uint32_t *Wh, *Wl; int k20;
            if (t < 4) { Wh = g_Wself_h; Wl = g_Wself_l; k20 = t*K2C; }
            else       { Wh = g_Wng_h;   Wl = g_Wng_l;   k20 = (t-4)*K2C; }
            stageB(Bh, Bl, Wh, Wl, k20, colbase, tid);
        }
        __syncthreads();
        mma_chunk(Ah, Al, Bh, Bl, acc, wm, wn, lane);
        __syncthreads();
    }

    #pragma unroll
    for (int mf = 0; mf < 2; mf++) {
        int r0 = rowbase + wm*32 + mf*16 + (lane >> 2);
        int r1 = r0 + 8;
        #pragma unroll
        for (int nf = 0; nf < 8; nf++) {
            int gc = colbase + wn*64 + nf*8 + 2*(lane & 3);
            *(float2*)&out[(size_t)r0*HID + gc] =
                make_float2(fmaxf(acc[mf][nf][0], 0.f), fmaxf(acc[mf][nf][1], 0.f));
            *(float2*)&out[(size_t)r1*HID + gc] =
                make_float2(fmaxf(acc[mf][nf][2], 0.f), fmaxf(acc[mf][nf][3], 0.f));
        }
    }
}

// ------------------------------------------------------------------
extern "C" void kernel_launch(void* const* d_in, const int* in_sizes, int n_in,
                              void* d_out, int out_size) {
    const int*   node_ids = (const int*)d_in[0];
    const int*   nbr_ev   = (const int*)d_in[1];
    const int*   ev_st    = (const int*)d_in[2];
    const int*   ev_dt    = (const int*)d_in[3];
    const int*   ev_et    = (const int*)d_in[4];
    const int*   ev_sid   = (const int*)d_in[5];
    const int*   ev_did   = (const int*)d_in[6];
    const int*   ev_ts    = (const int*)d_in[7];
    const float* ev_w     = (const float*)d_in[8];
    const float* emb0     = (const float*)d_in[9];
    const float* emb1     = (const float*)d_in[10];
    const float* edge_emb = (const float*)d_in[11];
    const float* edge_lin = (const float*)d_in[12];
    const float* mlp_w1   = (const float*)d_in[13];
    const float* mlp_b1   = (const float*)d_in[14];
    const float* mlp_w2   = (const float*)d_in[15];
    const float* mlp_b2   = (const float*)d_in[16];
    const float* wsrc     = (const float*)d_in[17];
    const float* wdst     = (const float*)d_in[18];
    const float* wself    = (const float*)d_in[19];
    const float* wneigh   = (const float*)d_in[20];
    float* out = (float*)d_out;

    size_t smem_dyn = (size_t)DYN_U32 * sizeof(uint32_t);
    cudaFuncSetAttribute(ev_kernel,  cudaFuncAttributeMaxDynamicSharedMemorySize, (int)smem_dyn);
    cudaFuncSetAttribute(out_kernel, cudaFuncAttributeMaxDynamicSharedMemorySize, (int)smem_dyn);

    prep_split<<<(HID/2*HID + 255)/256, 256>>>(wsrc, wdst, mlp_w2, wself, wneigh);
    prep_relb2<<<1, 256>>>(edge_emb, edge_lin, mlp_b2);

    dim3 gev(BE/BM, 2);
    ev_kernel<<<gev, 256, smem_dyn>>>(nbr_ev, ev_st, ev_dt, ev_et, ev_sid, ev_did,
                                      ev_ts, ev_w, emb0, emb1, mlp_w1, mlp_b1);
    dim3 gout(NB/BM, 2);
    out_kernel<<<gout, 256, smem_dyn>>>(node_ids, emb0, out);
}